// round 9
// baseline (speedup 1.0000x reference)
#include <cuda_runtime.h>
#include <cuda_bf16.h>
#include <cooperative_groups.h>

namespace cg = cooperative_groups;

#define BN_ 32
#define TN_ 1024
#define DN_ 1024
#define ON_ 256
#define CS_ 4
#define SC_ (TN_/CS_)   /* 256 s-rows per CTA */

// ---- device scratch (static: no runtime allocation) ----
__device__ __align__(128) __nv_bfloat16 g_UaH[(size_t)BN_*TN_*ON_]; // inputs@Ua + Ba2
__device__ __align__(128) __nv_bfloat16 g_IC [(size_t)BN_*TN_*ON_]; // inputs@Co
__device__ __align__(128) float         g_UoH[(size_t)BN_*TN_*ON_]; // inputs@Uo + Bo2
__device__ float g_w2[ON_];                                          // emb @ Wo

__device__ __forceinline__ float tanh_a(float x){
    float y; asm("tanh.approx.f32 %0, %1;" : "=f"(y) : "f"(x)); return y;
}

__device__ __forceinline__ void bf8(const uint4 u, float f[8]){
    f[0]=__int_as_float(u.x<<16); f[1]=__int_as_float(u.x&0xffff0000u);
    f[2]=__int_as_float(u.y<<16); f[3]=__int_as_float(u.y&0xffff0000u);
    f[4]=__int_as_float(u.z<<16); f[5]=__int_as_float(u.z&0xffff0000u);
    f[6]=__int_as_float(u.w<<16); f[7]=__int_as_float(u.w&0xffff0000u);
}

// ================= w2 = emb @ Wo =================
__global__ void __launch_bounds__(256) w2_kernel(const float* __restrict__ emb,
                                                 const float* __restrict__ Wo){
    int i = threadIdx.x;
    float a = 0.f;
    #pragma unroll 8
    for (int j=0;j<ON_;j++) a = fmaf(emb[i*ON_+j], Wo[j], a);
    g_w2[i] = a;
}

// ======= fused precompute: [32768,1024] @ 3x[1024,256] =======
// nt: 0-1 -> Ua (bf16 UaH, +Ba2) | 2-3 -> Co (bf16 IC) | 4-5 -> Uo (f32 UoH, +Bo2)
__global__ void __launch_bounds__(256) gemm_pre(
    const float* __restrict__ A,  const float* __restrict__ Ua,
    const float* __restrict__ Co, const float* __restrict__ Uo,
    const float* __restrict__ Ba2,const float* __restrict__ Bo2)
{
    __shared__ float As[16][128];
    __shared__ float Bs[16][128];
    const int tid = threadIdx.x;
    const int mt = blockIdx.x, nt = blockIdx.y;
    const int which = nt >> 1;
    const int ncol0 = (nt & 1) * 128;
    const float* Bmat = (which==0) ? Ua : ((which==1) ? Co : Uo);
    const int m0 = mt * 128;
    const int tx = tid & 15, ty = tid >> 4;

    float acc[8][8];
    #pragma unroll
    for (int i=0;i<8;i++)
        #pragma unroll
        for (int j=0;j<8;j++) acc[i][j]=0.f;

    for (int k0=0;k0<DN_;k0+=16){
        #pragma unroll
        for (int q=0;q<2;q++){
            int f4 = tid + q*256;
            int row = f4 >> 2, c4 = f4 & 3;
            float4 v = *(const float4*)&A[(size_t)(m0+row)*DN_ + k0 + c4*4];
            As[c4*4+0][row]=v.x; As[c4*4+1][row]=v.y;
            As[c4*4+2][row]=v.z; As[c4*4+3][row]=v.w;
        }
        #pragma unroll
        for (int q=0;q<2;q++){
            int f4 = tid + q*256;
            int kk = f4 >> 5, c4 = f4 & 31;
            *(float4*)&Bs[kk][c4*4] = *(const float4*)&Bmat[(size_t)(k0+kk)*ON_ + ncol0 + c4*4];
        }
        __syncthreads();
        #pragma unroll
        for (int kk=0;kk<16;kk++){
            float a[8], bb[8];
            *(float4*)&a[0]  = *(const float4*)&As[kk][ty*8];
            *(float4*)&a[4]  = *(const float4*)&As[kk][ty*8+4];
            *(float4*)&bb[0] = *(const float4*)&Bs[kk][tx*8];
            *(float4*)&bb[4] = *(const float4*)&Bs[kk][tx*8+4];
            #pragma unroll
            for (int i=0;i<8;i++)
                #pragma unroll
                for (int j=0;j<8;j++) acc[i][j] = fmaf(a[i], bb[j], acc[i][j]);
        }
        __syncthreads();
    }
    #pragma unroll
    for (int i=0;i<8;i++){
        int mrow = m0 + ty*8 + i;
        int trow = mrow & (TN_-1);
        #pragma unroll
        for (int j=0;j<8;j++){
            int c = ncol0 + tx*8 + j;
            float v = acc[i][j];
            size_t oi = (size_t)mrow*ON_ + c;
            if (which==0)      g_UaH[oi] = __float2bfloat16(v + Ba2[trow*ON_ + c]);
            else if (which==1) g_IC[oi]  = __float2bfloat16(v);
            else               g_UoH[oi] = v + Bo2[c];
        }
    }
}

// ============ persistent per-batch cluster recurrence ============
__global__ void __cluster_dims__(CS_,1,1) __launch_bounds__(256,1)
recur_kernel(const float* __restrict__ Wa,  const float* __restrict__ Va,
             const float* __restrict__ Ba1, const float* __restrict__ Ba3,
             const float* __restrict__ Bo3, const float* __restrict__ Bo4,
             float* __restrict__ out)
{
    extern __shared__ float s_WaT[];       // [64][256] this rank's Wa columns, transposed
    __shared__ float s_pred[ON_];
    __shared__ float s_q[ON_];
    __shared__ float s_was[ON_];
    __shared__ float s_wasq[64];           // exported WaS quarter
    __shared__ float s_ba1q[64];
    __shared__ float s_ba3[SC_];
    __shared__ float s_b34[ON_];           // Bo3 + Bo4
    __shared__ float s_w2[ON_];
    __shared__ float s_wc[8][ON_];         // per-warp coc partials
    __shared__ float s_wm[8], s_wl[8];
    __shared__ float s_cexp[ON_+2];        // exported CTA partial: c[256], m, l
    __shared__ float s_redA[8], s_redB[8], s_redC[8];

    cg::cluster_group cluster = cg::this_cluster();
    const int rank = blockIdx.x;           // 0..3 within cluster
    const int b    = blockIdx.y;           // batch
    const int tid  = threadIdx.x;
    const int w = tid >> 5, lane = tid & 31;

    // ---- one-time init ----
    s_pred[tid] = 0.f;
    s_ba3[tid]  = Ba3[rank*SC_ + tid];
    s_b34[tid]  = Bo3[tid] + Bo4[tid];
    s_w2[tid]   = g_w2[tid];
    if (tid < 64) s_ba1q[tid] = Ba1[rank*64 + tid];
    for (int idx = tid; idx < 64*ON_; idx += 256){
        int oo = idx >> 8, j = idx & 255;
        s_WaT[oo*ON_ + j] = Wa[j*ON_ + rank*64 + oo];
    }

    float va8[8];
    #pragma unroll
    for (int k=0;k<8;k++) va8[k] = Va[lane*8+k];

    const __nv_bfloat16* uahB = g_UaH + (size_t)b*TN_*ON_ + (size_t)rank*SC_*ON_;
    const __nv_bfloat16* icB  = g_IC  + (size_t)b*TN_*ON_ + (size_t)rank*SC_*ON_;
    const float* uohB = g_UoH + (size_t)b*TN_*ON_;
    float* outB = out + (size_t)b*TN_*ON_;

    // stable DSMEM peer pointers
    const float* peer_wasq[CS_];
    const float* peer_cexp[CS_];
    #pragma unroll
    for (int r=0;r<CS_;r++){
        peer_wasq[r] = (const float*)cluster.map_shared_rank((void*)s_wasq, r);
        peer_cexp[r] = (const float*)cluster.map_shared_rank((void*)s_cexp, r);
    }
    __syncthreads();

    const unsigned FULL = 0xffffffffu;

    for (int t=0; t<TN_; t++){
        // ---- phase 1: q = tanh(pred); woy = softmax(pred)·w2 ----
        float pv = s_pred[tid];
        s_q[tid] = tanh_a(pv);
        float m1 = pv;
        #pragma unroll
        for (int off=16; off; off>>=1) m1 = fmaxf(m1, __shfl_xor_sync(FULL, m1, off));
        if (lane==0) s_redC[w] = m1;
        __syncthreads();
        float pm = s_redC[0];
        #pragma unroll
        for (int r=1;r<8;r++) pm = fmaxf(pm, s_redC[r]);
        float e  = __expf(pv - pm);
        float en = e, ew = e * s_w2[tid];
        #pragma unroll
        for (int off=16; off; off>>=1){
            en += __shfl_xor_sync(FULL, en, off);
            ew += __shfl_xor_sync(FULL, ew, off);
        }
        if (lane==0){ s_redA[w]=en; s_redB[w]=ew; }
        __syncthreads();
        float sn=0.f, sw=0.f;
        #pragma unroll
        for (int r=0;r<8;r++){ sn+=s_redA[r]; sw+=s_redB[r]; }
        float woy = sw / sn;

        // ---- phase 2: this rank's WaS quarter (outputs rank*64 .. +63) ----
        float qr[8];
        #pragma unroll
        for (int k=0;k<8;k++) qr[k] = s_q[lane + 32*k];
        #pragma unroll
        for (int jj=0;jj<8;jj++){
            int oo = w*8 + jj;
            float p = 0.f;
            #pragma unroll
            for (int k=0;k<8;k++) p = fmaf(qr[k], s_WaT[oo*ON_ + lane + 32*k], p);
            #pragma unroll
            for (int off=16; off; off>>=1) p += __shfl_xor_sync(FULL, p, off);
            if (lane==0) s_wasq[oo] = p + s_ba1q[oo];
        }
        cluster.sync();   // #1: all WaS quarters published

        // ---- phase 4: gather full WaS ----
        s_was[tid] = peer_wasq[tid>>6][tid & 63];
        __syncthreads();

        // ---- phase 5: online-softmax score pass over own 256 rows ----
        float was8[8];
        #pragma unroll
        for (int k=0;k<8;k++) was8[k] = s_was[lane*8+k];
        float m = -__int_as_float(0x7f800000), l = 0.f, c[8];
        #pragma unroll
        for (int k=0;k<8;k++) c[k]=0.f;

        for (int i=0;i<32;i++){
            int s = w*32 + i;
            uint4 u = ((const uint4*)(uahB + (size_t)s*ON_))[lane];
            float f[8]; bf8(u, f);
            float p = 0.f;
            #pragma unroll
            for (int k=0;k<8;k++) p = fmaf(tanh_a(f[k] + was8[k]), va8[k], p);
            #pragma unroll
            for (int off=16; off; off>>=1) p += __shfl_xor_sync(FULL, p, off);
            float score = p + s_ba3[s];
            float mn = fmaxf(m, score);
            float scl = __expf(m - mn);       // 0 on first iter (m = -inf)
            float pe  = __expf(score - mn);
            l = l*scl + pe;
            uint4 v = ((const uint4*)(icB + (size_t)s*ON_))[lane];
            float g[8]; bf8(v, g);
            #pragma unroll
            for (int k=0;k<8;k++) c[k] = fmaf(c[k], scl, pe*g[k]);
            m = mn;
        }

        // ---- phase 6: combine 8 warps within CTA ----
        if (lane==0){ s_wm[w]=m; s_wl[w]=l; }
        #pragma unroll
        for (int k=0;k<8;k++) s_wc[w][lane*8+k] = c[k];
        __syncthreads();
        {
            float M = s_wm[0];
            #pragma unroll
            for (int r=1;r<8;r++) M = fmaxf(M, s_wm[r]);
            float sc_=0.f, sl_=0.f;
            #pragma unroll
            for (int r=0;r<8;r++){
                float e_ = __expf(s_wm[r]-M);
                sc_ = fmaf(s_wc[r][tid], e_, sc_);
                sl_ = fmaf(s_wl[r], e_, sl_);
            }
            s_cexp[tid] = sc_;
            if (tid==0){ s_cexp[ON_] = M; s_cexp[ON_+1] = sl_; }
        }
        cluster.sync();   // #2: all CTA partials published

        // ---- phase 8: cross-CTA combine + pred update (identical in all ranks) ----
        float mr[CS_], lr[CS_], M2 = -__int_as_float(0x7f800000);
        #pragma unroll
        for (int r=0;r<CS_;r++){
            mr[r] = peer_cexp[r][ON_];
            lr[r] = peer_cexp[r][ON_+1];
            M2 = fmaxf(M2, mr[r]);
        }
        float csum=0.f, L=0.f;
        #pragma unroll
        for (int r=0;r<CS_;r++){
            float e_ = __expf(mr[r]-M2);
            csum = fmaf(peer_cexp[r][tid], e_, csum);
            L    = fmaf(lr[r], e_, L);
        }
        float coc = csum / L;
        float uoh = uohB[(size_t)((t + TN_ - 1) & (TN_-1))*ON_ + tid];
        float pred = woy + uoh + coc + s_b34[tid];
        if (rank==0) outB[(size_t)t*ON_ + tid] = pred;
        s_pred[tid] = pred;
        __syncthreads();
    }
}

extern "C" void kernel_launch(void* const* d_in, const int* in_sizes, int n_in,
                              void* d_out, int out_size) {
    const float* inputs = (const float*)d_in[0];
    const float* Wa  = (const float*)d_in[1];
    const float* Ua  = (const float*)d_in[2];
    const float* Va  = (const float*)d_in[3];
    const float* Ba1 = (const float*)d_in[4];
    const float* Ba2 = (const float*)d_in[5];
    const float* Ba3 = (const float*)d_in[6];
    const float* Wo  = (const float*)d_in[7];
    const float* Uo  = (const float*)d_in[8];
    const float* Co  = (const float*)d_in[9];
    const float* Bo2 = (const float*)d_in[10];
    const float* Bo3 = (const float*)d_in[11];
    const float* Bo4 = (const float*)d_in[12];
    const float* emb = (const float*)d_in[13];
    float* out = (float*)d_out;

    static bool attr_done = false;
    if (!attr_done){
        cudaFuncSetAttribute(recur_kernel,
            cudaFuncAttributeMaxDynamicSharedMemorySize, 64*ON_*sizeof(float));
        attr_done = true;
    }

    w2_kernel<<<1, 256>>>(emb, Wo);
    gemm_pre<<<dim3((BN_*TN_)/128, 6), 256>>>(inputs, Ua, Co, Uo, Ba2, Bo2);
    recur_kernel<<<dim3(CS_, BN_, 1), 256, 64*ON_*sizeof(float)>>>(
        Wa, Va, Ba1, Ba3, Bo3, Bo4, out);
}